// round 15
// baseline (speedup 1.0000x reference)
#include <cuda_runtime.h>
#include <cstdint>

#define BSZ 8
#define CIN 256
#define COUT 256
#define HH 64
#define WW 64
#define KK (CIN * 9)          // 2304
#define NTOT (BSZ * HH * WW)  // 32768

#define BM 128
#define BN 256
#define BK 32
#define NITER (KK / BK)       // 72
#define THREADS 512

// Scratch
__device__ float g_wta[BSZ * COUT * KK];      // styled tap-major tf32 weights: [b][co][tap][ci]
__device__ float g_wsqT[CIN * COUT];          // transposed wsq: [ci][co]
__device__ float g_rsigma[BSZ * COUT];

// ---------------------------------------------------------------------------
__device__ __forceinline__ uint32_t smem_u32(const void* p) {
    uint32_t a;
    asm("{ .reg .u64 t; cvta.to.shared.u64 t, %1; cvt.u32.u64 %0, t; }" : "=r"(a) : "l"(p));
    return a;
}
__device__ __forceinline__ float to_tf32(float f) {
    uint32_t u;
    asm("cvt.rna.tf32.f32 %0, %1;" : "=r"(u) : "f"(f));
    return __uint_as_float(u);
}
__device__ __forceinline__ void ldsm_x4(uint32_t* r, uint32_t addr) {
    asm volatile("ldmatrix.sync.aligned.m8n8.x4.shared.b16 {%0,%1,%2,%3}, [%4];"
                 : "=r"(r[0]), "=r"(r[1]), "=r"(r[2]), "=r"(r[3]) : "r"(addr));
}
__device__ __forceinline__ void mma_tf32(float* d, const uint32_t* a, uint32_t b0, uint32_t b1) {
    asm volatile(
        "mma.sync.aligned.m16n8k8.row.col.f32.tf32.tf32.f32 "
        "{%0,%1,%2,%3}, {%4,%5,%6,%7}, {%8,%9}, {%0,%1,%2,%3};"
        : "+f"(d[0]), "+f"(d[1]), "+f"(d[2]), "+f"(d[3])
        : "r"(a[0]), "r"(a[1]), "r"(a[2]), "r"(a[3]), "r"(b0), "r"(b1));
}
__device__ __forceinline__ void cp16z(uint32_t dst, const void* src, uint32_t src_sz) {
    asm volatile("cp.async.cg.shared.global [%0], [%1], 16, %2;"
                 :: "r"(dst), "l"(src), "r"(src_sz) : "memory");
}
__device__ __forceinline__ void cp4z(uint32_t dst, const void* src, uint32_t src_sz) {
    asm volatile("cp.async.ca.shared.global [%0], [%1], 4, %2;"
                 :: "r"(dst), "l"(src), "r"(src_sz) : "memory");
}
#define CP_COMMIT() asm volatile("cp.async.commit_group;" ::: "memory")
#define CP_WAIT0()  asm volatile("cp.async.wait_group 0;" ::: "memory")

// ---------------------------------------------------------------------------
// Pre-kernels. Launch order: prep_w(b 0-3), sigma, prep_w(b 4-7), conv
// (keeps conv as the 4th launch so ncu captures it).
// ---------------------------------------------------------------------------
// prep_w: grid=(COUT, 4), 256 thr (ci). Styled tap-major tf32 weights.
// Coalesced gmem read via smem; stride-9 smem reads conflict-free.
__global__ void prep_w(const float* __restrict__ w, const float* __restrict__ style,
                       int b0) {
    __shared__ float sw[KK];
    const int co = blockIdx.x;
    const int b = b0 + blockIdx.y;
    for (int i = threadIdx.x; i < KK; i += 256)
        sw[i] = w[(size_t)co * KK + i];
    __syncthreads();
    const int ci = threadIdx.x;
    const float s = style[b * CIN + ci];
    float v[9];
    float sq = 0.f;
#pragma unroll
    for (int t = 0; t < 9; t++) {
        v[t] = sw[ci * 9 + t];
        sq += v[t] * v[t];
    }
    if (b == 0) g_wsqT[ci * COUT + co] = sq;
    float* dst = g_wta + ((size_t)(b * COUT + co)) * KK;
#pragma unroll
    for (int t = 0; t < 9; t++)
        dst[t * 256 + ci] = to_tf32(v[t] * s);   // coalesced over ci
}

// sigma: grid=B, 256 thr (co). Coalesced wsqT reads, 4 partial sums.
__global__ void sigma_kernel(const float* __restrict__ style) {
    __shared__ float s2[CIN];
    int b = blockIdx.x;
    for (int i = threadIdx.x; i < CIN; i += blockDim.x) {
        float s = style[b * CIN + i];
        s2[i] = s * s;
    }
    __syncthreads();
    int co = threadIdx.x;
    float a0 = 0.f, a1 = 0.f, a2 = 0.f, a3 = 0.f;
#pragma unroll 4
    for (int ci = 0; ci < CIN; ci += 4) {
        a0 += s2[ci + 0] * g_wsqT[(ci + 0) * COUT + co];
        a1 += s2[ci + 1] * g_wsqT[(ci + 1) * COUT + co];
        a2 += s2[ci + 2] * g_wsqT[(ci + 2) * COUT + co];
        a3 += s2[ci + 3] * g_wsqT[(ci + 3) * COUT + co];
    }
    g_rsigma[b * COUT + co] = rsqrtf((a0 + a1) + (a2 + a3) + 1e-8f);
}

// ---------------------------------------------------------------------------
// tf32 mma.sync implicit-GEMM conv (R10 proven body). 512 thr, 16 warps of
// 32x64, BK=32, 2-stage cp.async, 1 bar/iter. A = styled weights (per batch),
// B = raw NCHW x via strided 4B cp.async (coalesced across n within warp).
// ---------------------------------------------------------------------------
#define ROWF 36                       // floats per smem row (32 + 4 pad)
#define SA_F (BM * ROWF)              // 4608 floats
#define SB_F (BN * ROWF)              // 9216 floats
#define STG_F (SA_F + SB_F)
#define STG_B (STG_F * 4)             // 55296 B

__global__ __launch_bounds__(THREADS, 1)
void conv_mma(const float* __restrict__ x, float* __restrict__ out) {
    extern __shared__ float sm[];
    const uint32_t smb = smem_u32(sm);

    const int tid = threadIdx.x;
    const int lane = tid & 31;
    const int warp = tid >> 5;

    const int m0c = blockIdx.y * BM;
    const int n0c = blockIdx.x * BN;
    const int b = n0c >> 12;
    const float* xb = x + (size_t)b * CIN * 4096;   // NCHW batch base

    // --- A loader: 128 rows x 32 floats; 4 threads/row, 8 floats -> 2 cp16 ---
    const int arow = tid >> 2;
    const int aq   = (tid & 3) * 8;
    const float* wa_base = g_wta + ((size_t)(b * COUT + m0c + arow)) * KK + aq;
    const uint32_t a_sts = (uint32_t)((arow * ROWF + aq) * 4);

    // --- B loader: 256 rows, 2 threads/row, 16 ci-planes each -> 16 cp4 ---
    const int bn = tid >> 1;
    const int bh = (tid & 1) * 16;                  // ci offset within BK
    const int nn = n0c + bn;
    const int wc = nn & 63;
    const int hr = (nn >> 6) & 63;
    const uint32_t b_sts = (uint32_t)((SA_F + bn * ROWF + bh) * 4);

    // --- compute mapping: 16 warps as 4(M) x 4(N), warp tile 32x64 ---
    const int wm = (warp >> 2) * 32;
    const int wn = (warp & 3) * 64;
    const uint32_t a_byte = (uint32_t)(((wm + (lane & 15)) * ROWF + (lane >> 4) * 4) * 4);
    const uint32_t b_byte =
        (uint32_t)(((wn + (lane & 7) + ((lane >> 4) << 3)) * ROWF + ((lane >> 3) & 1) * 4) * 4);

    float acc[2][8][4];
#pragma unroll
    for (int i = 0; i < 2; i++)
#pragma unroll
        for (int j = 0; j < 8; j++)
#pragma unroll
            for (int q = 0; q < 4; q++) acc[i][j][q] = 0.f;

    // --- tap state (advanced every 8 load-tiles) ---
    int kh = 0, kw = 0;
    bool v0 = (hr > 0) && (wc > 0);
    uint32_t bsz = v0 ? 4u : 0u;
    const float* bsrc = v0 ? (xb + ((hr - 1) * 64 + (wc - 1)) + (size_t)bh * 4096) : xb;

    auto advance_tap = [&]() {
        kw++;
        if (kw == 3) { kw = 0; kh++; }
        int hs = hr + kh - 1;
        int ws = wc + kw - 1;
        bool v = ((unsigned)hs < 64u) && ((unsigned)ws < 64u);
        bsz = v ? 4u : 0u;
        bsrc = v ? (xb + (hs * 64 + ws) + (size_t)bh * 4096) : xb;
    };
    auto issue_loads = [&](int lt, int s) {
        const uint32_t sb = smb + (uint32_t)(s * STG_B);
        const float* wp = wa_base + (size_t)lt * BK;
        cp16z(sb + a_sts, wp, 16u);
        cp16z(sb + a_sts + 16u, wp + 4, 16u);
        // ci0 = (lt & 7) * 32 + bh; plane stride 4096 floats
        const float* p = bsrc + (size_t)((lt & 7) << 5) * 4096;
#pragma unroll
        for (int j = 0; j < 16; j++)
            cp4z(sb + b_sts + (uint32_t)(j * 4), p + (size_t)j * 4096, bsz);
        CP_COMMIT();
    };

    // ---- prologue: tile 0 (tap 0) ----
    issue_loads(0, 0);
    CP_WAIT0();
    __syncthreads();

    for (int it = 0; it < NITER; it++) {
        const int s = it & 1;
        const int lt = it + 1;
        if (lt < NITER) {
            if ((lt & 7) == 0) advance_tap();
            issue_loads(lt, s ^ 1);   // lands during compute below
        }

        // ---- compute on stage s: 4 k-substeps (R10 proven order) ----
        const uint32_t sAs = smb + (uint32_t)(s * STG_B);
        const uint32_t sBs = sAs + (uint32_t)(SA_F * 4);
#pragma unroll
        for (int ks = 0; ks < 4; ks++) {
            uint32_t afr[2][4], bfr[4][4];
#pragma unroll
            for (int mi = 0; mi < 2; mi++)
                ldsm_x4(afr[mi], sAs + a_byte + (uint32_t)(mi * 16 * ROWF * 4 + ks * 32));
#pragma unroll
            for (int nj = 0; nj < 4; nj++)
                ldsm_x4(bfr[nj], sBs + b_byte + (uint32_t)(nj * 16 * ROWF * 4 + ks * 32));
#pragma unroll
            for (int mi = 0; mi < 2; mi++)
#pragma unroll
                for (int nj = 0; nj < 4; nj++) {
                    mma_tf32(acc[mi][nj * 2 + 0], afr[mi], bfr[nj][0], bfr[nj][1]);
                    mma_tf32(acc[mi][nj * 2 + 1], afr[mi], bfr[nj][2], bfr[nj][3]);
                }
        }

        CP_WAIT0();
        __syncthreads();
    }

    // ---- epilogue: scale by rsigma, write NCHW ----
    const int gid = lane >> 2;
    const int tig = lane & 3;
    const int ncol0 = (n0c & 4095) + wn + tig * 2;
#pragma unroll
    for (int mi = 0; mi < 2; mi++) {
#pragma unroll
        for (int half = 0; half < 2; half++) {
            int co = m0c + wm + mi * 16 + gid + half * 8;
            float rs = g_rsigma[b * COUT + co];
            float* orow = out + (size_t)(b * COUT + co) * 4096 + ncol0;
#pragma unroll
            for (int nj8 = 0; nj8 < 8; nj8++) {
                float2 v;
                v.x = acc[mi][nj8][half * 2 + 0] * rs;
                v.y = acc[mi][nj8][half * 2 + 1] * rs;
                *(float2*)(orow + nj8 * 8) = v;
            }
        }
    }
}

// ---------------------------------------------------------------------------
extern "C" void kernel_launch(void* const* d_in, const int* in_sizes, int n_in,
                              void* d_out, int out_size) {
    const float* x     = (const float*)d_in[0];  // [8,256,64,64]
    const float* style = (const float*)d_in[1];  // [8,256]
    const float* w     = (const float*)d_in[2];  // [256,256,3,3]
    float* out = (float*)d_out;

    dim3 pgrid(COUT, 4);
    prep_w<<<pgrid, 256>>>(w, style, 0);     // batches 0-3 (includes wsqT)
    sigma_kernel<<<BSZ, 256>>>(style);
    prep_w<<<pgrid, 256>>>(w, style, 4);     // batches 4-7

    const int dyn = 2 * STG_B;  // 110592 B
    cudaFuncSetAttribute(conv_mma, cudaFuncAttributeMaxDynamicSharedMemorySize, dyn);
    dim3 grid(NTOT / BN, COUT / BM);  // (128, 2)
    conv_mma<<<grid, THREADS, dyn>>>(x, out);
}

// round 16
// speedup vs baseline: 1.2160x; 1.2160x over previous
#include <cuda_runtime.h>
#include <cstdint>

#define BSZ 8
#define CIN 256
#define COUT 256
#define HH 64
#define WW 64
#define KK (CIN * 9)          // 2304
#define NTOT (BSZ * HH * WW)  // 32768

#define BM 128
#define BN 256
#define BK 32
#define NITER (KK / BK)       // 72
#define THREADS 512

// Scratch
__device__ float g_xm[BSZ * HH * WW * CIN];   // NHWC modulated tf32 input
__device__ float g_wt[COUT * KK];             // tap-major tf32 weights: [co][tap][ci]
__device__ float g_wsqT[CIN * COUT];          // transposed wsq: [ci][co]
__device__ float g_rsigma[BSZ * COUT];

// ---------------------------------------------------------------------------
__device__ __forceinline__ uint32_t smem_u32(const void* p) {
    uint32_t a;
    asm("{ .reg .u64 t; cvta.to.shared.u64 t, %1; cvt.u32.u64 %0, t; }" : "=r"(a) : "l"(p));
    return a;
}
__device__ __forceinline__ float to_tf32(float f) {
    uint32_t u;
    asm("cvt.rna.tf32.f32 %0, %1;" : "=r"(u) : "f"(f));
    return __uint_as_float(u);
}
__device__ __forceinline__ void ldsm_x4(uint32_t* r, uint32_t addr) {
    asm volatile("ldmatrix.sync.aligned.m8n8.x4.shared.b16 {%0,%1,%2,%3}, [%4];"
                 : "=r"(r[0]), "=r"(r[1]), "=r"(r[2]), "=r"(r[3]) : "r"(addr));
}
__device__ __forceinline__ void mma_tf32(float* d, const uint32_t* a, uint32_t b0, uint32_t b1) {
    asm volatile(
        "mma.sync.aligned.m16n8k8.row.col.f32.tf32.tf32.f32 "
        "{%0,%1,%2,%3}, {%4,%5,%6,%7}, {%8,%9}, {%0,%1,%2,%3};"
        : "+f"(d[0]), "+f"(d[1]), "+f"(d[2]), "+f"(d[3])
        : "r"(a[0]), "r"(a[1]), "r"(a[2]), "r"(a[3]), "r"(b0), "r"(b1));
}
__device__ __forceinline__ void cp16z(uint32_t dst, const void* src, uint32_t src_sz) {
    asm volatile("cp.async.cg.shared.global [%0], [%1], 16, %2;"
                 :: "r"(dst), "l"(src), "r"(src_sz) : "memory");
}
#define CP_COMMIT() asm volatile("cp.async.commit_group;" ::: "memory")
#define CP_WAIT0()  asm volatile("cp.async.wait_group 0;" ::: "memory")

// ---------------------------------------------------------------------------
// Pre-kernels (3 before conv so conv is the 4th launch -> gets profiled)
// ---------------------------------------------------------------------------
// prep_w: grid=COUT, 256 thr. Coalesced read via smem; writes g_wt coalesced
// over ci; writes wsqT (transposed) so sigma reads coalesce.
__global__ void prep_w(const float* __restrict__ w) {
    __shared__ float sw[KK];
    const int co = blockIdx.x;
    for (int i = threadIdx.x; i < KK; i += 256)
        sw[i] = w[(size_t)co * KK + i];
    __syncthreads();
    const int ci = threadIdx.x;
    float v[9];
    float s = 0.f;
#pragma unroll
    for (int t = 0; t < 9; t++) {          // stride-9 smem: conflict-free (gcd(9,32)=1)
        v[t] = sw[ci * 9 + t];
        s += v[t] * v[t];
    }
    g_wsqT[ci * COUT + co] = s;
#pragma unroll
    for (int t = 0; t < 9; t++)
        g_wt[(size_t)co * KK + t * 256 + ci] = to_tf32(v[t]);   // coalesced over ci
}

// sigma: grid=B, 256 thr (co). Coalesced wsqT reads, 4 partial sums.
__global__ void sigma_kernel(const float* __restrict__ style) {
    __shared__ float s2[CIN];
    int b = blockIdx.x;
    for (int i = threadIdx.x; i < CIN; i += blockDim.x) {
        float s = style[b * CIN + i];
        s2[i] = s * s;
    }
    __syncthreads();
    int co = threadIdx.x;
    float a0 = 0.f, a1 = 0.f, a2 = 0.f, a3 = 0.f;
#pragma unroll 4
    for (int ci = 0; ci < CIN; ci += 4) {
        a0 += s2[ci + 0] * g_wsqT[(ci + 0) * COUT + co];
        a1 += s2[ci + 1] * g_wsqT[(ci + 1) * COUT + co];
        a2 += s2[ci + 2] * g_wsqT[(ci + 2) * COUT + co];
        a3 += s2[ci + 3] * g_wsqT[(ci + 3) * COUT + co];
    }
    g_rsigma[b * COUT + co] = rsqrtf((a0 + a1) + (a2 + a3) + 1e-8f);
}

__global__ void modx_nhwc(const float* __restrict__ x, const float* __restrict__ style) {
    const int b = blockIdx.x >> 6;
    const int h = blockIdx.x & 63;
    const int ci = threadIdx.x;
    const float s = style[b * 256 + ci];
    const float4* src = (const float4*)(x + (((size_t)b * 256 + ci) * 64 + h) * 64);
    float* dst = g_xm + ((size_t)(b * 64 + h) * 64) * 256 + ci;
#pragma unroll
    for (int q = 0; q < 16; q++) {
        float4 v = src[q];
        dst[(size_t)(q * 4 + 0) * 256] = to_tf32(v.x * s);
        dst[(size_t)(q * 4 + 1) * 256] = to_tf32(v.y * s);
        dst[(size_t)(q * 4 + 2) * 256] = to_tf32(v.z * s);
        dst[(size_t)(q * 4 + 3) * 256] = to_tf32(v.w * s);
    }
}

// ---------------------------------------------------------------------------
// tf32 mma.sync implicit-GEMM conv. R10 proven body: 512 thr, 16 warps of
// 32x64, BK=32, 2-stage cp.async, tap-major K, NHWC cp16 gather, 1 bar/iter.
// ---------------------------------------------------------------------------
#define ROWF 36                       // floats per smem row (32 + 4 pad)
#define SA_F (BM * ROWF)              // 4608 floats
#define SB_F (BN * ROWF)              // 9216 floats
#define STG_F (SA_F + SB_F)
#define STG_B (STG_F * 4)             // 55296 B

__global__ __launch_bounds__(THREADS, 1)
void conv_mma(float* __restrict__ out) {
    extern __shared__ float sm[];
    const uint32_t smb = smem_u32(sm);

    const int tid = threadIdx.x;
    const int lane = tid & 31;
    const int warp = tid >> 5;

    const int m0c = blockIdx.y * BM;
    const int n0c = blockIdx.x * BN;
    const int b = n0c >> 12;
    const float* xm_b = g_xm + (size_t)b * 4096 * 256;

    // --- A loader: 128 rows x 32 floats; 4 threads/row, 8 floats -> 2 cp16 ---
    const int arow = tid >> 2;
    const int aq   = (tid & 3) * 8;
    const float* wa_base = g_wt + (size_t)(m0c + arow) * KK + aq;
    const uint32_t a_sts = (uint32_t)((arow * ROWF + aq) * 4);

    // --- B loader: 256 rows, 2 threads/row, 16 contiguous ci -> 4 cp16 ---
    const int bn = tid >> 1;
    const int bh = (tid & 1) * 16;
    const int nn = n0c + bn;
    const int wc = nn & 63;
    const int hr = (nn >> 6) & 63;
    const uint32_t b_sts = (uint32_t)((SA_F + bn * ROWF + bh) * 4);

    // --- compute mapping: 16 warps as 4(M) x 4(N), warp tile 32x64 ---
    const int wm = (warp >> 2) * 32;
    const int wn = (warp & 3) * 64;
    const uint32_t a_byte = (uint32_t)(((wm + (lane & 15)) * ROWF + (lane >> 4) * 4) * 4);
    const uint32_t b_byte =
        (uint32_t)(((wn + (lane & 7) + ((lane >> 4) << 3)) * ROWF + ((lane >> 3) & 1) * 4) * 4);

    float acc[2][8][4];
#pragma unroll
    for (int i = 0; i < 2; i++)
#pragma unroll
        for (int j = 0; j < 8; j++)
#pragma unroll
            for (int q = 0; q < 4; q++) acc[i][j][q] = 0.f;

    // --- tap state (advanced every 8 load-tiles) ---
    int kh = 0, kw = 0;
    bool v0 = (hr > 0) && (wc > 0);
    uint32_t bsz = v0 ? 16u : 0u;
    const float* bsrc = v0 ? (xm_b + (size_t)((hr - 1) * 64 + (wc - 1)) * 256 + bh) : xm_b;

    auto advance_tap = [&]() {
        kw++;
        if (kw == 3) { kw = 0; kh++; }
        int hs = hr + kh - 1;
        int ws = wc + kw - 1;
        bool v = ((unsigned)hs < 64u) && ((unsigned)ws < 64u);
        bsz = v ? 16u : 0u;
        bsrc = v ? (xm_b + (size_t)(hs * 64 + ws) * 256 + bh) : xm_b;
    };
    auto issue_loads = [&](int lt, int s) {
        const uint32_t sb = smb + (uint32_t)(s * STG_B);
        const float* wp = wa_base + (size_t)lt * BK;
        cp16z(sb + a_sts, wp, 16u);
        cp16z(sb + a_sts + 16u, wp + 4, 16u);
        const float* p = bsrc + ((lt & 7) << 5);
        cp16z(sb + b_sts, p, bsz);
        cp16z(sb + b_sts + 16u, p + 4, bsz);
        cp16z(sb + b_sts + 32u, p + 8, bsz);
        cp16z(sb + b_sts + 48u, p + 12, bsz);
        CP_COMMIT();
    };

    // ---- prologue: tile 0 (tap 0) ----
    issue_loads(0, 0);
    CP_WAIT0();
    __syncthreads();

    for (int it = 0; it < NITER; it++) {
        const int s = it & 1;
        const int lt = it + 1;
        if (lt < NITER) {
            if ((lt & 7) == 0) advance_tap();
            issue_loads(lt, s ^ 1);   // lands during compute below
        }

        // ---- compute on stage s: 4 k-substeps (R10 proven order) ----
        const uint32_t sAs = smb + (uint32_t)(s * STG_B);
        const uint32_t sBs = sAs + (uint32_t)(SA_F * 4);
#pragma unroll
        for (int ks = 0; ks < 4; ks++) {
            uint32_t afr[2][4], bfr[4][4];
#pragma unroll
            for (int mi = 0; mi < 2; mi++)
                ldsm_x4(afr[mi], sAs + a_byte + (uint32_t)(mi * 16 * ROWF * 4 + ks * 32));
#pragma unroll
            for (int nj = 0; nj < 4; nj++)
                ldsm_x4(bfr[nj], sBs + b_byte + (uint32_t)(nj * 16 * ROWF * 4 + ks * 32));
#pragma unroll
            for (int mi = 0; mi < 2; mi++)
#pragma unroll
                for (int nj = 0; nj < 4; nj++) {
                    mma_tf32(acc[mi][nj * 2 + 0], afr[mi], bfr[nj][0], bfr[nj][1]);
                    mma_tf32(acc[mi][nj * 2 + 1], afr[mi], bfr[nj][2], bfr[nj][3]);
                }
        }

        CP_WAIT0();
        __syncthreads();
    }

    // ---- epilogue: scale by rsigma, write NCHW ----
    const int gid = lane >> 2;
    const int tig = lane & 3;
    const int ncol0 = (n0c & 4095) + wn + tig * 2;
#pragma unroll
    for (int mi = 0; mi < 2; mi++) {
#pragma unroll
        for (int half = 0; half < 2; half++) {
            int co = m0c + wm + mi * 16 + gid + half * 8;
            float rs = g_rsigma[b * COUT + co];
            float* orow = out + (size_t)(b * COUT + co) * 4096 + ncol0;
#pragma unroll
            for (int nj8 = 0; nj8 < 8; nj8++) {
                float2 v;
                v.x = acc[mi][nj8][half * 2 + 0] * rs;
                v.y = acc[mi][nj8][half * 2 + 1] * rs;
                *(float2*)(orow + nj8 * 8) = v;
            }
        }
    }
}

// ---------------------------------------------------------------------------
extern "C" void kernel_launch(void* const* d_in, const int* in_sizes, int n_in,
                              void* d_out, int out_size) {
    const float* x     = (const float*)d_in[0];  // [8,256,64,64]
    const float* style = (const float*)d_in[1];  // [8,256]
    const float* w     = (const float*)d_in[2];  // [256,256,3,3]
    float* out = (float*)d_out;

    prep_w<<<COUT, 256>>>(w);
    sigma_kernel<<<BSZ, 256>>>(style);
    modx_nhwc<<<BSZ * HH, 256>>>(x, style);

    const int dyn = 2 * STG_B;  // 110592 B
    cudaFuncSetAttribute(conv_mma, cudaFuncAttributeMaxDynamicSharedMemorySize, dyn);
    dim3 grid(NTOT / BN, COUT / BM);  // (128, 2)
    conv_mma<<<grid, THREADS, dyn>>>(out);
}